// round 1
// baseline (speedup 1.0000x reference)
#include <cuda_runtime.h>
#include <cstdint>
#include <cstddef>

// ---------------------------------------------------------------------------
// Swin window attention, TF32 tensor-core pipeline:
//   K1: qkv = x @ qkv_w^T + qkv_b   (q pre-scaled)  -> g_q/g_k/g_v scratch
//   K2: per (window, head): S = qK^T + bias + mask; P = softmax(S); O = P V
//   K3: out = attn @ proj_w^T + proj_b
// ---------------------------------------------------------------------------

#define N_TOK   49
#define N_HEADS 12
#define HEAD_D  32
#define MODEL_D 384
#define NWIN    64
#define B_WIN   8192
#define M_TOT   (B_WIN * N_TOK)          // 401408
#define ATTN_SCALE 0.17677669529663687f  // 1/sqrt(32)

// Scratch: 4 x 616 MB static device arrays (allocation-free rule: __device__ globals)
__device__ float g_q[(size_t)B_WIN * N_HEADS * N_TOK * HEAD_D];
__device__ float g_k[(size_t)B_WIN * N_HEADS * N_TOK * HEAD_D];
__device__ float g_v[(size_t)B_WIN * N_HEADS * N_TOK * HEAD_D];
__device__ float g_att[(size_t)B_WIN * N_TOK * MODEL_D];

__device__ __forceinline__ uint32_t f2tf(float f) {
    uint32_t u;
    asm("cvt.rna.tf32.f32 %0, %1;" : "=r"(u) : "f"(f));
    return u;
}

__device__ __forceinline__ void mma_tf32(float d[4], const uint32_t a[4], const uint32_t b[2]) {
    asm volatile(
        "mma.sync.aligned.m16n8k8.row.col.f32.tf32.tf32.f32 "
        "{%0,%1,%2,%3}, {%4,%5,%6,%7}, {%8,%9}, {%0,%1,%2,%3};\n"
        : "+f"(d[0]), "+f"(d[1]), "+f"(d[2]), "+f"(d[3])
        : "r"(a[0]), "r"(a[1]), "r"(a[2]), "r"(a[3]),
          "r"(b[0]), "r"(b[1]));
}

// ---------------------------------------------------------------------------
// GEMM: C[M, NOUT] = A[M,384] @ W[NOUT,384]^T + bias
// Block tile 128x64, BK=32, 256 threads (8 warps in 4x2), warp tile 32x32.
// smem pitch 36 floats -> fragment LDS banks == lane id (conflict-free).
// EPI=0: scatter into g_q/g_k/g_v (q scaled). EPI=1: write to out.
// ---------------------------------------------------------------------------
template<int EPI>
__global__ void __launch_bounds__(256) gemm_tf32_kernel(
    const float* __restrict__ A, const float* __restrict__ W,
    const float* __restrict__ bias, float* __restrict__ out)
{
    extern __shared__ float smem[];
    float* As = smem;                    // [2][128][36]
    float* Bs = smem + 2 * 128 * 36;     // [2][64][36]

    const int tid  = threadIdx.x;
    const int lane = tid & 31;
    const int warp = tid >> 5;
    const int g    = lane >> 2;
    const int tg   = lane & 3;
    const int wm   = (warp & 3) * 32;
    const int wn   = (warp >> 2) * 32;

    const long m0 = (long)blockIdx.x * 128;
    const int  n0 = blockIdx.y * 64;

    const int ar = tid >> 1;            // 0..127
    const int ac = (tid & 1) * 16;      // 0/16
    const int br = tid >> 2;            // 0..63
    const int bc = (tid & 3) * 8;       // 0..24

    const float* Abase = (EPI == 0) ? A : (const float*)g_att;
    const float* Ag = Abase + (m0 + ar) * MODEL_D + ac;
    const float* Wg = W + (long)(n0 + br) * MODEL_D + bc;

    float4 areg[4];
    float4 breg[2];
    float acc[2][4][4];
#pragma unroll
    for (int i = 0; i < 2; i++)
#pragma unroll
        for (int j = 0; j < 4; j++)
#pragma unroll
            for (int r = 0; r < 4; r++) acc[i][j][r] = 0.f;

    // prologue: tile 0 -> regs -> smem[0]
#pragma unroll
    for (int i = 0; i < 4; i++) areg[i] = *(const float4*)(Ag + 4 * i);
#pragma unroll
    for (int i = 0; i < 2; i++) breg[i] = *(const float4*)(Wg + 4 * i);
    {
        float* ap = As + ar * 36 + ac;
#pragma unroll
        for (int i = 0; i < 4; i++) {
            uint4 u;
            u.x = f2tf(areg[i].x); u.y = f2tf(areg[i].y);
            u.z = f2tf(areg[i].z); u.w = f2tf(areg[i].w);
            *(uint4*)(ap + 4 * i) = u;
        }
        float* bp = Bs + br * 36 + bc;
#pragma unroll
        for (int i = 0; i < 2; i++) {
            uint4 u;
            u.x = f2tf(breg[i].x); u.y = f2tf(breg[i].y);
            u.z = f2tf(breg[i].z); u.w = f2tf(breg[i].w);
            *(uint4*)(bp + 4 * i) = u;
        }
    }
    __syncthreads();

#pragma unroll 1
    for (int kt = 0; kt < 12; kt++) {
        const int s = kt & 1;
        if (kt < 11) {  // prefetch next k-tile into registers
            const float* Ap = Ag + (kt + 1) * 32;
            const float* Wp = Wg + (kt + 1) * 32;
#pragma unroll
            for (int i = 0; i < 4; i++) areg[i] = *(const float4*)(Ap + 4 * i);
#pragma unroll
            for (int i = 0; i < 2; i++) breg[i] = *(const float4*)(Wp + 4 * i);
        }
        const float* Ab = As + s * (128 * 36);
        const float* Bb = Bs + s * (64 * 36);
#pragma unroll
        for (int kk = 0; kk < 4; kk++) {
            const int k0 = kk * 8;
            uint32_t afr[2][4];
#pragma unroll
            for (int mf = 0; mf < 2; mf++) {
                const int r = wm + mf * 16 + g;
                afr[mf][0] = __float_as_uint(Ab[r * 36 + k0 + tg]);
                afr[mf][1] = __float_as_uint(Ab[(r + 8) * 36 + k0 + tg]);
                afr[mf][2] = __float_as_uint(Ab[r * 36 + k0 + tg + 4]);
                afr[mf][3] = __float_as_uint(Ab[(r + 8) * 36 + k0 + tg + 4]);
            }
            uint32_t bfr[4][2];
#pragma unroll
            for (int nf = 0; nf < 4; nf++) {
                const int c = wn + nf * 8 + g;
                bfr[nf][0] = __float_as_uint(Bb[c * 36 + k0 + tg]);
                bfr[nf][1] = __float_as_uint(Bb[c * 36 + k0 + tg + 4]);
            }
#pragma unroll
            for (int mf = 0; mf < 2; mf++)
#pragma unroll
                for (int nf = 0; nf < 4; nf++)
                    mma_tf32(acc[mf][nf], afr[mf], bfr[nf]);
        }
        if (kt < 11) {  // store prefetched tile into the other buffer
            const int s2 = (kt + 1) & 1;
            float* ap = As + s2 * (128 * 36) + ar * 36 + ac;
#pragma unroll
            for (int i = 0; i < 4; i++) {
                uint4 u;
                u.x = f2tf(areg[i].x); u.y = f2tf(areg[i].y);
                u.z = f2tf(areg[i].z); u.w = f2tf(areg[i].w);
                *(uint4*)(ap + 4 * i) = u;
            }
            float* bp = Bs + s2 * (64 * 36) + br * 36 + bc;
#pragma unroll
            for (int i = 0; i < 2; i++) {
                uint4 u;
                u.x = f2tf(breg[i].x); u.y = f2tf(breg[i].y);
                u.z = f2tf(breg[i].z); u.w = f2tf(breg[i].w);
                *(uint4*)(bp + 4 * i) = u;
            }
        }
        __syncthreads();
    }

    // epilogue
#pragma unroll
    for (int mf = 0; mf < 2; mf++) {
#pragma unroll
        for (int nf = 0; nf < 4; nf++) {
#pragma unroll
            for (int r = 0; r < 4; r++) {
                const int rr = wm + mf * 16 + g + ((r & 2) ? 8 : 0);
                const int cc = wn + nf * 8 + tg * 2 + (r & 1);
                const long grow = m0 + rr;
                const int  gcol = n0 + cc;
                float v = acc[mf][nf][r] + bias[gcol];
                if (EPI == 0) {
                    const int t3  = gcol / MODEL_D;
                    const int rem = gcol - t3 * MODEL_D;
                    const int hh  = rem >> 5;
                    const int dd  = rem & 31;
                    const long bb = grow / N_TOK;
                    const int  ii = (int)(grow - bb * N_TOK);
                    if (t3 == 0) v *= ATTN_SCALE;
                    float* dst = (t3 == 0) ? g_q : ((t3 == 1) ? g_k : g_v);
                    dst[((bb * N_HEADS + hh) * N_TOK + ii) * HEAD_D + dd] = v;
                } else {
                    out[grow * MODEL_D + gcol] = v;
                }
            }
        }
    }
}

// ---------------------------------------------------------------------------
// Attention: one warp per (window b, head h). 4 heads per 128-thread block.
// Per-warp smem (floats): qs[64][36], ks[64][36], vts[32][60], ss[64][60]
// S = Q K^T (m=64pad, n=56pad, k=32) ; softmax over j<49 ; O = P V (k=56pad)
// ---------------------------------------------------------------------------
#define WARP_SMEM (64*36 + 64*36 + 32*60 + 64*60)   // 10368 floats

__global__ void __launch_bounds__(128) attn_kernel(
    const float* __restrict__ table,
    const int*   __restrict__ rpi,
    const float* __restrict__ mask)
{
    extern __shared__ float sm[];
    const int lane = threadIdx.x & 31;
    const int warp = threadIdx.x >> 5;
    const int g    = lane >> 2;
    const int tg   = lane & 3;
    const int b    = blockIdx.x;
    const int h    = blockIdx.y * 4 + warp;

    float* qs  = sm + warp * WARP_SMEM;  // [64][36]
    float* ks  = qs + 64 * 36;           // [64][36]
    float* vts = ks + 64 * 36;           // [32][60]  (V transposed: [d][j])
    float* ss  = vts + 32 * 60;          // [64][60]

    // zero-fill entire per-warp region (pads must be exact zeros)
    {
        float4 z = make_float4(0.f, 0.f, 0.f, 0.f);
        float4* p = (float4*)qs;
        for (int i = lane; i < WARP_SMEM / 4; i += 32) p[i] = z;
    }
    __syncwarp();

    // load q,k,v for this (b,h); convert to tf32 on store
    const size_t base = ((size_t)b * N_HEADS + h) * (N_TOK * HEAD_D);
    {
        const float4* qg = (const float4*)(g_q + base);
        const float4* kg = (const float4*)(g_k + base);
        const float4* vg = (const float4*)(g_v + base);
        for (int f = lane; f < (N_TOK * HEAD_D) / 4; f += 32) {
            const int r  = f >> 3;         // token row
            const int c0 = (f & 7) * 4;    // head-dim col
            float4 v = qg[f];
            float* p = qs + r * 36 + c0;
            p[0] = __uint_as_float(f2tf(v.x)); p[1] = __uint_as_float(f2tf(v.y));
            p[2] = __uint_as_float(f2tf(v.z)); p[3] = __uint_as_float(f2tf(v.w));
            v = kg[f];
            p = ks + r * 36 + c0;
            p[0] = __uint_as_float(f2tf(v.x)); p[1] = __uint_as_float(f2tf(v.y));
            p[2] = __uint_as_float(f2tf(v.z)); p[3] = __uint_as_float(f2tf(v.w));
            v = vg[f];
            vts[(c0 + 0) * 60 + r] = __uint_as_float(f2tf(v.x));
            vts[(c0 + 1) * 60 + r] = __uint_as_float(f2tf(v.y));
            vts[(c0 + 2) * 60 + r] = __uint_as_float(f2tf(v.z));
            vts[(c0 + 3) * 60 + r] = __uint_as_float(f2tf(v.w));
        }
    }
    __syncwarp();

    // ---- S = Q K^T + bias + mask ----
    const int maskbase = (b & (NWIN - 1)) * (N_TOK * N_TOK);
#pragma unroll 1
    for (int mf = 0; mf < 4; mf++) {
        float c7[7][4];
#pragma unroll
        for (int nf = 0; nf < 7; nf++)
#pragma unroll
            for (int r = 0; r < 4; r++) c7[nf][r] = 0.f;
#pragma unroll
        for (int kk = 0; kk < 4; kk++) {
            const int k0 = kk * 8;
            uint32_t a[4];
            const int rq = mf * 16 + g;
            a[0] = __float_as_uint(qs[rq * 36 + k0 + tg]);
            a[1] = __float_as_uint(qs[(rq + 8) * 36 + k0 + tg]);
            a[2] = __float_as_uint(qs[rq * 36 + k0 + tg + 4]);
            a[3] = __float_as_uint(qs[(rq + 8) * 36 + k0 + tg + 4]);
#pragma unroll
            for (int nf = 0; nf < 7; nf++) {
                const int c = nf * 8 + g;
                uint32_t bq[2];
                bq[0] = __float_as_uint(ks[c * 36 + k0 + tg]);
                bq[1] = __float_as_uint(ks[c * 36 + k0 + tg + 4]);
                mma_tf32(c7[nf], a, bq);
            }
        }
#pragma unroll
        for (int nf = 0; nf < 7; nf++) {
#pragma unroll
            for (int r = 0; r < 4; r++) {
                const int i = mf * 16 + g + ((r & 2) ? 8 : 0);
                const int j = nf * 8 + tg * 2 + (r & 1);
                float v = c7[nf][r];
                if (i < N_TOK && j < N_TOK)
                    v += table[rpi[i * N_TOK + j] * N_HEADS + h]
                       + mask[maskbase + i * N_TOK + j];
                ss[i * 60 + j] = v;
            }
        }
    }
    __syncwarp();

    // ---- softmax over j<49 per row; output stored as tf32 ----
    for (int r = lane; r < N_TOK; r += 32) {
        float* row = ss + r * 60;
        float mx = row[0];
        for (int j = 1; j < N_TOK; j++) mx = fmaxf(mx, row[j]);
        float sum = 0.f;
        for (int j = 0; j < N_TOK; j++) {
            float e = __expf(row[j] - mx);
            sum += e;
            row[j] = e;
        }
        const float inv = 1.f / sum;
        for (int j = 0; j < N_TOK; j++)
            row[j] = __uint_as_float(f2tf(row[j] * inv));
    }
    __syncwarp();

    // ---- O = P V ----
#pragma unroll 1
    for (int mf = 0; mf < 4; mf++) {
        float c4[4][4];
#pragma unroll
        for (int nf = 0; nf < 4; nf++)
#pragma unroll
            for (int r = 0; r < 4; r++) c4[nf][r] = 0.f;
#pragma unroll
        for (int kk = 0; kk < 7; kk++) {
            const int k0 = kk * 8;
            uint32_t a[4];
            const int rp = mf * 16 + g;
            a[0] = __float_as_uint(ss[rp * 60 + k0 + tg]);
            a[1] = __float_as_uint(ss[(rp + 8) * 60 + k0 + tg]);
            a[2] = __float_as_uint(ss[rp * 60 + k0 + tg + 4]);
            a[3] = __float_as_uint(ss[(rp + 8) * 60 + k0 + tg + 4]);
#pragma unroll
            for (int nf = 0; nf < 4; nf++) {
                const int c = nf * 8 + g;
                uint32_t bq[2];
                bq[0] = __float_as_uint(vts[c * 60 + k0 + tg]);
                bq[1] = __float_as_uint(vts[c * 60 + k0 + tg + 4]);
                mma_tf32(c4[nf], a, bq);
            }
        }
#pragma unroll
        for (int nf = 0; nf < 4; nf++) {
#pragma unroll
            for (int r = 0; r < 4; r++) {
                const int i = mf * 16 + g + ((r & 2) ? 8 : 0);
                const int d = nf * 8 + tg * 2 + (r & 1);
                if (i < N_TOK)
                    g_att[((size_t)b * N_TOK + i) * MODEL_D + h * HEAD_D + d] = c4[nf][r];
            }
        }
    }
}

// ---------------------------------------------------------------------------
extern "C" void kernel_launch(void* const* d_in, const int* in_sizes, int n_in,
                              void* d_out, int out_size)
{
    (void)in_sizes; (void)n_in; (void)out_size;
    const float* x      = (const float*)d_in[0];
    const float* mask   = (const float*)d_in[1];
    const float* table  = (const float*)d_in[2];
    const float* qkv_w  = (const float*)d_in[3];
    const float* qkv_b  = (const float*)d_in[4];
    const float* proj_w = (const float*)d_in[5];
    const float* proj_b = (const float*)d_in[6];
    const int*   rpi    = (const int*)d_in[7];
    float* out = (float*)d_out;

    const int gemm_smem = (2 * 128 * 36 + 2 * 64 * 36) * 4;   // 55296 B
    const int attn_smem = 4 * WARP_SMEM * 4;                  // 165888 B

    cudaFuncSetAttribute(gemm_tf32_kernel<0>, cudaFuncAttributeMaxDynamicSharedMemorySize, gemm_smem);
    cudaFuncSetAttribute(gemm_tf32_kernel<1>, cudaFuncAttributeMaxDynamicSharedMemorySize, gemm_smem);
    cudaFuncSetAttribute(attn_kernel,         cudaFuncAttributeMaxDynamicSharedMemorySize, attn_smem);

    // K1: qkv projection (M=401408, N=1152, K=384)
    gemm_tf32_kernel<0><<<dim3(M_TOT / 128, 1152 / 64), 256, gemm_smem>>>(x, qkv_w, qkv_b, nullptr);
    // K2: windowed attention, one warp per (window, head)
    attn_kernel<<<dim3(B_WIN, N_HEADS / 4), 128, attn_smem>>>(table, rpi, mask);
    // K3: output projection (M=401408, N=384, K=384)
    gemm_tf32_kernel<1><<<dim3(M_TOT / 128, 384 / 64), 256, gemm_smem>>>(nullptr, proj_w, proj_b, out);
}

// round 10
// speedup vs baseline: 1.0645x; 1.0645x over previous
#include <cuda_runtime.h>
#include <cstdint>
#include <cstddef>

// ---------------------------------------------------------------------------
// Swin window attention, legacy tf32 mma.sync pipeline (tcgen05 unavailable:
// harness compiles PTX at compute_103, 'a'-features rejected by ptxas).
//   K1: qkv = x @ qkv_w^T + qkv_b   (tf32 GEMM, 64x64 warp tiles) -> g_q/g_k/g_v
//   K2: per (window, head) attention (unchanged from R1)
//   K3: out = attn @ proj_w^T + proj_b
// R1 evidence: 32x32 warp tiles = 256 LDS bytes/MMA = 2x crossbar budget.
// 64x64 tiles halve it to 128 B/MMA (crossbar-balanced with HMMA issue).
// ---------------------------------------------------------------------------

#define N_TOK   49
#define N_HEADS 12
#define HEAD_D  32
#define MODEL_D 384
#define NWIN    64
#define B_WIN   8192
#define M_TOT   (B_WIN * N_TOK)          // 401408
#define ATTN_SCALE 0.17677669529663687f  // 1/sqrt(32)

__device__ float g_q[(size_t)B_WIN * N_HEADS * N_TOK * HEAD_D];
__device__ float g_k[(size_t)B_WIN * N_HEADS * N_TOK * HEAD_D];
__device__ float g_v[(size_t)B_WIN * N_HEADS * N_TOK * HEAD_D];
__device__ float g_att[(size_t)B_WIN * N_TOK * MODEL_D];

__device__ __forceinline__ uint32_t f2tf(float f) {
    uint32_t u;
    asm("cvt.rna.tf32.f32 %0, %1;" : "=r"(u) : "f"(f));
    return u;
}

__device__ __forceinline__ void mma_tf32(float d[4], const uint32_t a[4], const uint32_t b[2]) {
    asm volatile(
        "mma.sync.aligned.m16n8k8.row.col.f32.tf32.tf32.f32 "
        "{%0,%1,%2,%3}, {%4,%5,%6,%7}, {%8,%9}, {%0,%1,%2,%3};\n"
        : "+f"(d[0]), "+f"(d[1]), "+f"(d[2]), "+f"(d[3])
        : "r"(a[0]), "r"(a[1]), "r"(a[2]), "r"(a[3]),
          "r"(b[0]), "r"(b[1]));
}

// ---------------------------------------------------------------------------
// GEMM: C[M, 128-per-blockIdx.y] = A[M,384] @ W^T + bias
// Block tile 256(M) x 128(N), BK=16, 256 threads = 8 warps (4 M x 2 N),
// warp tile 64x64 -> 128 LDS bytes per MMA (vs 256 in the R1 32x32 design).
// Double-buffered smem; gmem->reg->cvt.rna->smem staging (keeps tf32 RN
// rounding; raw-bit staging would truncate RZ and risk the 1e-3 threshold).
// smem pitch 20 floats: bank = (20r+c)&31, quad-lane map covers all banks.
// EPI=0: scatter into g_q/g_k/g_v (+bias, q scaled). EPI=1: out (+bias).
// ---------------------------------------------------------------------------
#define GP 20
#define SM_AS      0
#define SM_BS      (2 * 256 * GP)
#define SM_BIAS    (2 * 256 * GP + 2 * 128 * GP)
#define GEMM_SMEMF (2 * 256 * GP + 2 * 128 * GP + 128)   // floats
#define GEMM_SMEMB (GEMM_SMEMF * 4)                       // 61952 bytes

template<int EPI>
__global__ void __launch_bounds__(256) gemm_big(
    const float* __restrict__ A, const float* __restrict__ W,
    const float* __restrict__ bias, float* __restrict__ out)
{
    extern __shared__ float sm[];
    float* As    = sm + SM_AS;     // [2][256][GP]
    float* Bs    = sm + SM_BS;     // [2][128][GP]
    float* biasS = sm + SM_BIAS;   // [128]

    const int tid  = threadIdx.x;
    const int lane = tid & 31;
    const int warp = tid >> 5;
    const int g    = lane >> 2;
    const int tg   = lane & 3;
    const int wm   = (warp & 3) * 64;   // 4 M-warps
    const int wn   = (warp >> 2) * 64;  // 2 N-warps

    const long m0 = (long)blockIdx.x * 256;
    const int  ny = blockIdx.y;
    const int  n0 = ny * 128;

    if (tid < 128) biasS[tid] = bias[n0 + tid];

    const float* Abase = (EPI == 0) ? A : (const float*)g_att;
    // staging: thread tid owns A row tid (16 floats/chunk = 4 float4),
    //          and half of B row tid>>1 (8 floats = 2 float4)
    const float* Ag = Abase + (m0 + tid) * MODEL_D;
    const float* Wg = W + (long)(n0 + (tid >> 1)) * MODEL_D + (tid & 1) * 8;

    float acc[4][8][4];
#pragma unroll
    for (int mf = 0; mf < 4; mf++)
#pragma unroll
        for (int nf = 0; nf < 8; nf++)
#pragma unroll
            for (int r = 0; r < 4; r++) acc[mf][nf][r] = 0.f;

    float4 pa[4], pb[2];

    // prologue: chunk 0 -> regs -> smem buf 0
#pragma unroll
    for (int i = 0; i < 4; i++) pa[i] = *(const float4*)(Ag + 4 * i);
#pragma unroll
    for (int i = 0; i < 2; i++) pb[i] = *(const float4*)(Wg + 4 * i);
    {
        float* ap = As + tid * GP;
#pragma unroll
        for (int i = 0; i < 4; i++) {
            uint4 u;
            u.x = f2tf(pa[i].x); u.y = f2tf(pa[i].y);
            u.z = f2tf(pa[i].z); u.w = f2tf(pa[i].w);
            *(uint4*)(ap + 4 * i) = u;
        }
        float* bp = Bs + (tid >> 1) * GP + (tid & 1) * 8;
#pragma unroll
        for (int i = 0; i < 2; i++) {
            uint4 u;
            u.x = f2tf(pb[i].x); u.y = f2tf(pb[i].y);
            u.z = f2tf(pb[i].z); u.w = f2tf(pb[i].w);
            *(uint4*)(bp + 4 * i) = u;
        }
    }
    __syncthreads();

#pragma unroll 1
    for (int c = 0; c < 24; c++) {
        const int buf = c & 1;
        if (c < 23) {
            const int kc = (c + 1) * 16;
#pragma unroll
            for (int i = 0; i < 4; i++) pa[i] = *(const float4*)(Ag + kc + 4 * i);
#pragma unroll
            for (int i = 0; i < 2; i++) pb[i] = *(const float4*)(Wg + kc + 4 * i);
        }
        const float* Ab = As + buf * (256 * GP);
        const float* Bb = Bs + buf * (128 * GP);
#pragma unroll
        for (int kk = 0; kk < 2; kk++) {
            const int k0 = kk * 8;
            uint32_t af[4][4];
#pragma unroll
            for (int mf = 0; mf < 4; mf++) {
                const int r = wm + mf * 16 + g;
                af[mf][0] = __float_as_uint(Ab[r * GP + k0 + tg]);
                af[mf][1] = __float_as_uint(Ab[(r + 8) * GP + k0 + tg]);
                af[mf][2] = __float_as_uint(Ab[r * GP + k0 + tg + 4]);
                af[mf][3] = __float_as_uint(Ab[(r + 8) * GP + k0 + tg + 4]);
            }
            uint32_t bf[8][2];
#pragma unroll
            for (int nf = 0; nf < 8; nf++) {
                const int cr = wn + nf * 8 + g;
                bf[nf][0] = __float_as_uint(Bb[cr * GP + k0 + tg]);
                bf[nf][1] = __float_as_uint(Bb[cr * GP + k0 + tg + 4]);
            }
#pragma unroll
            for (int mf = 0; mf < 4; mf++)
#pragma unroll
                for (int nf = 0; nf < 8; nf++)
                    mma_tf32(acc[mf][nf], af[mf], bf[nf]);
        }
        if (c < 23) {
            const int b2 = (c + 1) & 1;
            float* ap = As + b2 * (256 * GP) + tid * GP;
#pragma unroll
            for (int i = 0; i < 4; i++) {
                uint4 u;
                u.x = f2tf(pa[i].x); u.y = f2tf(pa[i].y);
                u.z = f2tf(pa[i].z); u.w = f2tf(pa[i].w);
                *(uint4*)(ap + 4 * i) = u;
            }
            float* bp = Bs + b2 * (128 * GP) + (tid >> 1) * GP + (tid & 1) * 8;
#pragma unroll
            for (int i = 0; i < 2; i++) {
                uint4 u;
                u.x = f2tf(pb[i].x); u.y = f2tf(pb[i].y);
                u.z = f2tf(pb[i].z); u.w = f2tf(pb[i].w);
                *(uint4*)(bp + 4 * i) = u;
            }
        }
        __syncthreads();
    }

    // ---------------- epilogue ----------------
    const int t3      = (EPI == 0) ? (ny / 3) : 0;
    const int rembase = (EPI == 0) ? ((ny % 3) * 128) : 0;
    float* dstT = (EPI == 0) ? ((t3 == 0) ? g_q : ((t3 == 1) ? g_k : g_v)) : out;
    const float scl = (EPI == 0 && t3 == 0) ? ATTN_SCALE : 1.0f;

#pragma unroll
    for (int mf = 0; mf < 4; mf++) {
#pragma unroll
        for (int h2 = 0; h2 < 2; h2++) {
            const long m = m0 + wm + mf * 16 + g + h2 * 8;
            long rowoff;
            if (EPI == 0) {
                const long bb = m / N_TOK;
                const int  ii = (int)(m - bb * N_TOK);
                rowoff = bb * (N_HEADS * N_TOK * HEAD_D) + (long)ii * HEAD_D;
            } else {
                rowoff = m * MODEL_D;
            }
#pragma unroll
            for (int nf = 0; nf < 8; nf++) {
                const int cc = wn + nf * 8 + tg * 2;
                float2 v;
                v.x = (acc[mf][nf][h2 * 2 + 0] + biasS[cc])     * scl;
                v.y = (acc[mf][nf][h2 * 2 + 1] + biasS[cc + 1]) * scl;
                if (EPI == 0) {
                    const int rc = rembase + cc;
                    const int hh = rc >> 5, dd = rc & 31;
                    *(float2*)(dstT + rowoff + (long)hh * (N_TOK * HEAD_D) + dd) = v;
                } else {
                    *(float2*)(dstT + rowoff + n0 + cc) = v;
                }
            }
        }
    }
}

// ---------------------------------------------------------------------------
// Attention (unchanged from R1, which passed): one warp per (window, head).
// ---------------------------------------------------------------------------
#define WARP_SMEM (64*36 + 64*36 + 32*60 + 64*60)   // 10368 floats

__global__ void __launch_bounds__(128) attn_kernel(
    const float* __restrict__ table,
    const int*   __restrict__ rpi,
    const float* __restrict__ mask)
{
    extern __shared__ float sm[];
    const int lane = threadIdx.x & 31;
    const int warp = threadIdx.x >> 5;
    const int g    = lane >> 2;
    const int tg   = lane & 3;
    const int b    = blockIdx.x;
    const int h    = blockIdx.y * 4 + warp;

    float* qs  = sm + warp * WARP_SMEM;  // [64][36]
    float* ks  = qs + 64 * 36;           // [64][36]
    float* vts = ks + 64 * 36;           // [32][60]
    float* ss  = vts + 32 * 60;          // [64][60]

    {
        float4 z = make_float4(0.f, 0.f, 0.f, 0.f);
        float4* p = (float4*)qs;
        for (int i = lane; i < WARP_SMEM / 4; i += 32) p[i] = z;
    }
    __syncwarp();

    const size_t base = ((size_t)b * N_HEADS + h) * (N_TOK * HEAD_D);
    {
        const float4* qg = (const float4*)(g_q + base);
        const float4* kg = (const float4*)(g_k + base);
        const float4* vg = (const float4*)(g_v + base);
        for (int f = lane; f < (N_TOK * HEAD_D) / 4; f += 32) {
            const int r  = f >> 3;
            const int c0 = (f & 7) * 4;
            float4 v = qg[f];
            float* p = qs + r * 36 + c0;
            p[0] = __uint_as_float(f2tf(v.x)); p[1] = __uint_as_float(f2tf(v.y));
            p[2] = __uint_as_float(f2tf(v.z)); p[3] = __uint_as_float(f2tf(v.w));
            v = kg[f];
            p = ks + r * 36 + c0;
            p[0] = __uint_as_float(f2tf(v.x)); p[1] = __uint_as_float(f2tf(v.y));
            p[2] = __uint_as_float(f2tf(v.z)); p[3] = __uint_as_float(f2tf(v.w));
            v = vg[f];
            vts[(c0 + 0) * 60 + r] = __uint_as_float(f2tf(v.x));
            vts[(c0 + 1) * 60 + r] = __uint_as_float(f2tf(v.y));
            vts[(c0 + 2) * 60 + r] = __uint_as_float(f2tf(v.z));
            vts[(c0 + 3) * 60 + r] = __uint_as_float(f2tf(v.w));
        }
    }
    __syncwarp();

    const int maskbase = (b & (NWIN - 1)) * (N_TOK * N_TOK);
#pragma unroll 1
    for (int mf = 0; mf < 4; mf++) {
        float c7[7][4];
#pragma unroll
        for (int nf = 0; nf < 7; nf++)
#pragma unroll
            for (int r = 0; r < 4; r++) c7[nf][r] = 0.f;
#pragma unroll
        for (int kk = 0; kk < 4; kk++) {
            const int k0 = kk * 8;
            uint32_t a[4];
            const int rq = mf * 16 + g;
            a[0] = __float_as_uint(qs[rq * 36 + k0 + tg]);
            a[1] = __float_as_uint(qs[(rq + 8) * 36 + k0 + tg]);
            a[2] = __float_as_uint(qs[rq * 36 + k0 + tg + 4]);
            a[3] = __float_as_uint(qs[(rq + 8) * 36 + k0 + tg + 4]);
#pragma unroll
            for (int nf = 0; nf < 7; nf++) {
                const int c = nf * 8 + g;
                uint32_t bq[2];
                bq[0] = __float_as_uint(ks[c * 36 + k0 + tg]);
                bq[1] = __float_as_uint(ks[c * 36 + k0 + tg + 4]);
                mma_tf32(c7[nf], a, bq);
            }
        }
#pragma unroll
        for (int nf = 0; nf < 7; nf++) {
#pragma unroll
            for (int r = 0; r < 4; r++) {
                const int i = mf * 16 + g + ((r & 2) ? 8 : 0);
                const int j = nf * 8 + tg * 2 + (r & 1);
                float v = c7[nf][r];
                if (i < N_TOK && j < N_TOK)
                    v += table[rpi[i * N_TOK + j] * N_HEADS + h]
                       + mask[maskbase + i * N_TOK + j];
                ss[i * 60 + j] = v;
            }
        }
    }
    __syncwarp();

    for (int r = lane; r < N_TOK; r += 32) {
        float* row = ss + r * 60;
        float mx = row[0];
        for (int j = 1; j < N_TOK; j++) mx = fmaxf(mx, row[j]);
        float sum = 0.f;
        for (int j = 0; j < N_TOK; j++) {
            float e = __expf(row[j] - mx);
            sum += e;
            row[j] = e;
        }
        const float inv = 1.f / sum;
        for (int j = 0; j < N_TOK; j++)
            row[j] = __uint_as_float(f2tf(row[j] * inv));
    }
    __syncwarp();

#pragma unroll 1
    for (int mf = 0; mf < 4; mf++) {
        float c4[4][4];
#pragma unroll
        for (int nf = 0; nf < 4; nf++)
#pragma unroll
            for (int r = 0; r < 4; r++) c4[nf][r] = 0.f;
#pragma unroll
        for (int kk = 0; kk < 7; kk++) {
            const int k0 = kk * 8;
            uint32_t a[4];
            const int rp = mf * 16 + g;
            a[0] = __float_as_uint(ss[rp * 60 + k0 + tg]);
            a[1] = __float_as_uint(ss[(rp + 8) * 60 + k0 + tg]);
            a[2] = __float_as_uint(ss[rp * 60 + k0 + tg + 4]);
            a[3] = __float_as_uint(ss[(rp + 8) * 60 + k0 + tg + 4]);
#pragma unroll
            for (int nf = 0; nf < 4; nf++) {
                const int c = nf * 8 + g;
                uint32_t bq[2];
                bq[0] = __float_as_uint(vts[c * 60 + k0 + tg]);
                bq[1] = __float_as_uint(vts[c * 60 + k0 + tg + 4]);
                mma_tf32(c4[nf], a, bq);
            }
        }
#pragma unroll
        for (int nf = 0; nf < 4; nf++) {
#pragma unroll
            for (int r = 0; r < 4; r++) {
                const int i = mf * 16 + g + ((r & 2) ? 8 : 0);
                const int d = nf * 8 + tg * 2 + (r & 1);
                if (i < N_TOK)
                    g_att[((size_t)b * N_TOK + i) * MODEL_D + h * HEAD_D + d] = c4[nf][r];
            }
        }
    }
}

// ---------------------------------------------------------------------------
extern "C" void kernel_launch(void* const* d_in, const int* in_sizes, int n_in,
                              void* d_out, int out_size)
{
    (void)in_sizes; (void)n_in; (void)out_size;
    const float* x      = (const float*)d_in[0];
    const float* mask   = (const float*)d_in[1];
    const float* table  = (const float*)d_in[2];
    const float* qkv_w  = (const float*)d_in[3];
    const float* qkv_b  = (const float*)d_in[4];
    const float* proj_w = (const float*)d_in[5];
    const float* proj_b = (const float*)d_in[6];
    const int*   rpi    = (const int*)d_in[7];
    float* out = (float*)d_out;

    const int attn_smem = 4 * WARP_SMEM * 4;   // 165888 B

    cudaFuncSetAttribute(gemm_big<0>, cudaFuncAttributeMaxDynamicSharedMemorySize, GEMM_SMEMB);
    cudaFuncSetAttribute(gemm_big<1>, cudaFuncAttributeMaxDynamicSharedMemorySize, GEMM_SMEMB);
    cudaFuncSetAttribute(attn_kernel, cudaFuncAttributeMaxDynamicSharedMemorySize, attn_smem);

    // K1: qkv projection (M=401408, N=1152, K=384) -> g_q/g_k/g_v
    gemm_big<0><<<dim3(M_TOT / 256, 1152 / 128), 256, GEMM_SMEMB>>>(x, qkv_w, qkv_b, nullptr);
    // K2: windowed attention -> g_att
    attn_kernel<<<dim3(B_WIN, N_HEADS / 4), 128, attn_smem>>>(table, rpi, mask);
    // K3: output projection (M=401408, N=384, K=384) -> out
    gemm_big<1><<<dim3(M_TOT / 256, 384 / 128), 256, GEMM_SMEMB>>>(nullptr, proj_w, proj_b, out);
}

// round 11
// speedup vs baseline: 1.3928x; 1.3085x over previous
#include <cuda_runtime.h>
#include <cstdint>
#include <cstddef>

// ---------------------------------------------------------------------------
// Swin window attention, legacy tf32 mma.sync (tcgen05 blocked: harness
// compiles PTX at compute_103; 'a'-features rejected by ptxas).
// R10 evidence: K2 (attention) = ~7.2ms of 7.9ms (4 warps/SM, 166 waves,
// per-block gather chains). This round rewrites K2:
//   - smem/warp 41.5KB -> 15KB (only S/P matrix) => 3 blocks/SM = 12 warps
//   - Q/K/V fragments gmem->reg direct (K,V loop-invariant, resident)
//   - rel-pos bias + mask pre-summed into g_bm by a tiny kernel
// GEMMs unchanged from the R10 pass (control).
// ---------------------------------------------------------------------------

#define N_TOK   49
#define N_HEADS 12
#define HEAD_D  32
#define MODEL_D 384
#define NWIN    64
#define B_WIN   8192
#define M_TOT   (B_WIN * N_TOK)          // 401408
#define ATTN_SCALE 0.17677669529663687f  // 1/sqrt(32)

__device__ float g_q[(size_t)B_WIN * N_HEADS * N_TOK * HEAD_D];
__device__ float g_k[(size_t)B_WIN * N_HEADS * N_TOK * HEAD_D];
__device__ float g_v[(size_t)B_WIN * N_HEADS * N_TOK * HEAD_D];
__device__ float g_att[(size_t)B_WIN * N_TOK * MODEL_D];
__device__ float g_bm[(size_t)NWIN * N_HEADS * N_TOK * N_TOK];   // bias+mask, 7.4MB

__device__ __forceinline__ uint32_t f2tf(float f) {
    uint32_t u;
    asm("cvt.rna.tf32.f32 %0, %1;" : "=r"(u) : "f"(f));
    return u;
}

__device__ __forceinline__ void mma_tf32(float d[4], const uint32_t a[4], const uint32_t b[2]) {
    asm volatile(
        "mma.sync.aligned.m16n8k8.row.col.f32.tf32.tf32.f32 "
        "{%0,%1,%2,%3}, {%4,%5,%6,%7}, {%8,%9}, {%0,%1,%2,%3};\n"
        : "+f"(d[0]), "+f"(d[1]), "+f"(d[2]), "+f"(d[3])
        : "r"(a[0]), "r"(a[1]), "r"(a[2]), "r"(a[3]),
          "r"(b[0]), "r"(b[1]));
}

// ---------------------------------------------------------------------------
// K0: g_bm[w][h][i][j] = table[rpi[i,j]*H + h] + mask[w][i][j]
// ---------------------------------------------------------------------------
__global__ void bias_precompute(const float* __restrict__ table,
                                const int*   __restrict__ rpi,
                                const float* __restrict__ mask)
{
    const int w = blockIdx.x;   // window 0..63
    const int h = blockIdx.y;   // head 0..11
    float* dst = g_bm + ((size_t)w * N_HEADS + h) * (N_TOK * N_TOK);
    const float* mk = mask + (size_t)w * (N_TOK * N_TOK);
    for (int ij = threadIdx.x; ij < N_TOK * N_TOK; ij += blockDim.x)
        dst[ij] = table[rpi[ij] * N_HEADS + h] + mk[ij];
}

// ---------------------------------------------------------------------------
// GEMM (unchanged from R10 pass): block 256x128, BK=16, 64x64 warp tiles.
// ---------------------------------------------------------------------------
#define GP 20
#define SM_AS      0
#define SM_BS      (2 * 256 * GP)
#define SM_BIAS    (2 * 256 * GP + 2 * 128 * GP)
#define GEMM_SMEMF (2 * 256 * GP + 2 * 128 * GP + 128)   // floats
#define GEMM_SMEMB (GEMM_SMEMF * 4)                       // 61952 bytes

template<int EPI>
__global__ void __launch_bounds__(256) gemm_big(
    const float* __restrict__ A, const float* __restrict__ W,
    const float* __restrict__ bias, float* __restrict__ out)
{
    extern __shared__ float sm[];
    float* As    = sm + SM_AS;
    float* Bs    = sm + SM_BS;
    float* biasS = sm + SM_BIAS;

    const int tid  = threadIdx.x;
    const int lane = tid & 31;
    const int warp = tid >> 5;
    const int g    = lane >> 2;
    const int tg   = lane & 3;
    const int wm   = (warp & 3) * 64;
    const int wn   = (warp >> 2) * 64;

    const long m0 = (long)blockIdx.x * 256;
    const int  ny = blockIdx.y;
    const int  n0 = ny * 128;

    if (tid < 128) biasS[tid] = bias[n0 + tid];

    const float* Abase = (EPI == 0) ? A : (const float*)g_att;
    const float* Ag = Abase + (m0 + tid) * MODEL_D;
    const float* Wg = W + (long)(n0 + (tid >> 1)) * MODEL_D + (tid & 1) * 8;

    float acc[4][8][4];
#pragma unroll
    for (int mf = 0; mf < 4; mf++)
#pragma unroll
        for (int nf = 0; nf < 8; nf++)
#pragma unroll
            for (int r = 0; r < 4; r++) acc[mf][nf][r] = 0.f;

    float4 pa[4], pb[2];

#pragma unroll
    for (int i = 0; i < 4; i++) pa[i] = *(const float4*)(Ag + 4 * i);
#pragma unroll
    for (int i = 0; i < 2; i++) pb[i] = *(const float4*)(Wg + 4 * i);
    {
        float* ap = As + tid * GP;
#pragma unroll
        for (int i = 0; i < 4; i++) {
            uint4 u;
            u.x = f2tf(pa[i].x); u.y = f2tf(pa[i].y);
            u.z = f2tf(pa[i].z); u.w = f2tf(pa[i].w);
            *(uint4*)(ap + 4 * i) = u;
        }
        float* bp = Bs + (tid >> 1) * GP + (tid & 1) * 8;
#pragma unroll
        for (int i = 0; i < 2; i++) {
            uint4 u;
            u.x = f2tf(pb[i].x); u.y = f2tf(pb[i].y);
            u.z = f2tf(pb[i].z); u.w = f2tf(pb[i].w);
            *(uint4*)(bp + 4 * i) = u;
        }
    }
    __syncthreads();

#pragma unroll 1
    for (int c = 0; c < 24; c++) {
        const int buf = c & 1;
        if (c < 23) {
            const int kc = (c + 1) * 16;
#pragma unroll
            for (int i = 0; i < 4; i++) pa[i] = *(const float4*)(Ag + kc + 4 * i);
#pragma unroll
            for (int i = 0; i < 2; i++) pb[i] = *(const float4*)(Wg + kc + 4 * i);
        }
        const float* Ab = As + buf * (256 * GP);
        const float* Bb = Bs + buf * (128 * GP);
#pragma unroll
        for (int kk = 0; kk < 2; kk++) {
            const int k0 = kk * 8;
            uint32_t af[4][4];
#pragma unroll
            for (int mf = 0; mf < 4; mf++) {
                const int r = wm + mf * 16 + g;
                af[mf][0] = __float_as_uint(Ab[r * GP + k0 + tg]);
                af[mf][1] = __float_as_uint(Ab[(r + 8) * GP + k0 + tg]);
                af[mf][2] = __float_as_uint(Ab[r * GP + k0 + tg + 4]);
                af[mf][3] = __float_as_uint(Ab[(r + 8) * GP + k0 + tg + 4]);
            }
            uint32_t bf[8][2];
#pragma unroll
            for (int nf = 0; nf < 8; nf++) {
                const int cr = wn + nf * 8 + g;
                bf[nf][0] = __float_as_uint(Bb[cr * GP + k0 + tg]);
                bf[nf][1] = __float_as_uint(Bb[cr * GP + k0 + tg + 4]);
            }
#pragma unroll
            for (int mf = 0; mf < 4; mf++)
#pragma unroll
                for (int nf = 0; nf < 8; nf++)
                    mma_tf32(acc[mf][nf], af[mf], bf[nf]);
        }
        if (c < 23) {
            const int b2 = (c + 1) & 1;
            float* ap = As + b2 * (256 * GP) + tid * GP;
#pragma unroll
            for (int i = 0; i < 4; i++) {
                uint4 u;
                u.x = f2tf(pa[i].x); u.y = f2tf(pa[i].y);
                u.z = f2tf(pa[i].z); u.w = f2tf(pa[i].w);
                *(uint4*)(ap + 4 * i) = u;
            }
            float* bp = Bs + b2 * (128 * GP) + (tid >> 1) * GP + (tid & 1) * 8;
#pragma unroll
            for (int i = 0; i < 2; i++) {
                uint4 u;
                u.x = f2tf(pb[i].x); u.y = f2tf(pb[i].y);
                u.z = f2tf(pb[i].z); u.w = f2tf(pb[i].w);
                *(uint4*)(bp + 4 * i) = u;
            }
        }
        __syncthreads();
    }

    const int t3      = (EPI == 0) ? (ny / 3) : 0;
    const int rembase = (EPI == 0) ? ((ny % 3) * 128) : 0;
    float* dstT = (EPI == 0) ? ((t3 == 0) ? g_q : ((t3 == 1) ? g_k : g_v)) : out;
    const float scl = (EPI == 0 && t3 == 0) ? ATTN_SCALE : 1.0f;

#pragma unroll
    for (int mf = 0; mf < 4; mf++) {
#pragma unroll
        for (int h2 = 0; h2 < 2; h2++) {
            const long m = m0 + wm + mf * 16 + g + h2 * 8;
            long rowoff;
            if (EPI == 0) {
                const long bb = m / N_TOK;
                const int  ii = (int)(m - bb * N_TOK);
                rowoff = bb * (N_HEADS * N_TOK * HEAD_D) + (long)ii * HEAD_D;
            } else {
                rowoff = m * MODEL_D;
            }
#pragma unroll
            for (int nf = 0; nf < 8; nf++) {
                const int cc = wn + nf * 8 + tg * 2;
                float2 v;
                v.x = (acc[mf][nf][h2 * 2 + 0] + biasS[cc])     * scl;
                v.y = (acc[mf][nf][h2 * 2 + 1] + biasS[cc + 1]) * scl;
                if (EPI == 0) {
                    const int rc = rembase + cc;
                    const int hh = rc >> 5, dd = rc & 31;
                    *(float2*)(dstT + rowoff + (long)hh * (N_TOK * HEAD_D) + dd) = v;
                } else {
                    *(float2*)(dstT + rowoff + n0 + cc) = v;
                }
            }
        }
    }
}

// ---------------------------------------------------------------------------
// K2 v2: one warp per (window, head); only S/P in smem (64x60 f32 = 15KB/warp,
// 60-pitch => conflict-free A-frag quads). Q/K/V frags gmem->reg, predicated
// at the 49-row tail. 3 blocks/SM (launch_bounds), 12 warps.
// ---------------------------------------------------------------------------
#define SSP 60
#define ATTN_WARP_F (64 * SSP)             // 3840 floats / warp
#define ATTN_SMEMB  (4 * ATTN_WARP_F * 4)  // 61440 B / block

__global__ void __launch_bounds__(128, 3) attn_kernel2()
{
    extern __shared__ float sm[];
    const int lane = threadIdx.x & 31;
    const int warp = threadIdx.x >> 5;
    const int g    = lane >> 2;
    const int tg   = lane & 3;
    const int b    = blockIdx.x;
    const int h    = blockIdx.y * 4 + warp;
    float* ss = sm + warp * ATTN_WARP_F;

    const size_t base = ((size_t)b * N_HEADS + h) * (N_TOK * HEAD_D);
    const float* gq = g_q + base;
    const float* gk = g_k + base;
    const float* gv = g_v + base;
    const float* bm = g_bm + ((size_t)(b & (NWIN - 1)) * N_HEADS + h) * (N_TOK * N_TOK);

    // K fragments (B-operand of S = Q K^T): loop-invariant, resident.
    uint32_t kb[7][4][2];
#pragma unroll
    for (int nf = 0; nf < 7; nf++) {
        const int c = nf * 8 + g;
#pragma unroll
        for (int kk = 0; kk < 4; kk++) {
            const int k0 = kk * 8;
            kb[nf][kk][0] = (c < N_TOK) ? f2tf(gk[c * HEAD_D + k0 + tg])     : 0u;
            kb[nf][kk][1] = (c < N_TOK) ? f2tf(gk[c * HEAD_D + k0 + tg + 4]) : 0u;
        }
    }

    // ---- S = Q K^T + (bias+mask) -> ss ----
#pragma unroll 1
    for (int mf = 0; mf < 4; mf++) {
        const int rq = mf * 16 + g;
        uint32_t qa[4][4];
#pragma unroll
        for (int kk = 0; kk < 4; kk++) {
            const int k0 = kk * 8;
            qa[kk][0] = (rq < N_TOK)     ? f2tf(gq[rq * HEAD_D + k0 + tg])           : 0u;
            qa[kk][1] = (rq + 8 < N_TOK) ? f2tf(gq[(rq + 8) * HEAD_D + k0 + tg])     : 0u;
            qa[kk][2] = (rq < N_TOK)     ? f2tf(gq[rq * HEAD_D + k0 + tg + 4])       : 0u;
            qa[kk][3] = (rq + 8 < N_TOK) ? f2tf(gq[(rq + 8) * HEAD_D + k0 + tg + 4]) : 0u;
        }
        float c7[7][4];
#pragma unroll
        for (int nf = 0; nf < 7; nf++)
#pragma unroll
            for (int r = 0; r < 4; r++) c7[nf][r] = 0.f;
#pragma unroll
        for (int kk = 0; kk < 4; kk++)
#pragma unroll
            for (int nf = 0; nf < 7; nf++)
                mma_tf32(c7[nf], qa[kk], kb[nf][kk]);
#pragma unroll
        for (int nf = 0; nf < 7; nf++) {
#pragma unroll
            for (int r = 0; r < 4; r++) {
                const int i = mf * 16 + g + ((r & 2) ? 8 : 0);
                const int j = nf * 8 + tg * 2 + (r & 1);
                float v = 0.f;
                if (i < N_TOK && j < N_TOK)
                    v = c7[nf][r] + bm[i * N_TOK + j];
                ss[i * SSP + j] = v;   // pads written as exact 0
            }
        }
    }
    __syncwarp();

    // ---- softmax over j<49, per-lane rows; P stored as tf32 ----
    for (int r = lane; r < N_TOK; r += 32) {
        float* row = ss + r * SSP;
        float mx = row[0];
        for (int j = 1; j < N_TOK; j++) mx = fmaxf(mx, row[j]);
        float sum = 0.f;
        for (int j = 0; j < N_TOK; j++) {
            float e = __expf(row[j] - mx);
            sum += e;
            row[j] = e;
        }
        const float inv = 1.f / sum;
        for (int j = 0; j < N_TOK; j++)
            row[j] = __uint_as_float(f2tf(row[j] * inv));
    }
    __syncwarp();

    // V fragments (B-operand of O = P V): loop-invariant, resident.
    uint32_t vb[4][7][2];
#pragma unroll
    for (int nf = 0; nf < 4; nf++) {
        const int d = nf * 8 + g;
#pragma unroll
        for (int kk = 0; kk < 7; kk++) {
            const int j0 = kk * 8;
            vb[nf][kk][0] = (j0 + tg < N_TOK)     ? f2tf(gv[(j0 + tg) * HEAD_D + d])     : 0u;
            vb[nf][kk][1] = (j0 + tg + 4 < N_TOK) ? f2tf(gv[(j0 + tg + 4) * HEAD_D + d]) : 0u;
        }
    }

    // ---- O = P V -> g_att ----
#pragma unroll 1
    for (int mf = 0; mf < 4; mf++) {
        const int rp = mf * 16 + g;
        float c4[4][4];
#pragma unroll
        for (int nf = 0; nf < 4; nf++)
#pragma unroll
            for (int r = 0; r < 4; r++) c4[nf][r] = 0.f;
#pragma unroll
        for (int kk = 0; kk < 7; kk++) {
            const int k0 = kk * 8;
            uint32_t pa[4];
            pa[0] = __float_as_uint(ss[rp * SSP + k0 + tg]);
            pa[1] = __float_as_uint(ss[(rp + 8) * SSP + k0 + tg]);
            pa[2] = __float_as_uint(ss[rp * SSP + k0 + tg + 4]);
            pa[3] = __float_as_uint(ss[(rp + 8) * SSP + k0 + tg + 4]);
#pragma unroll
            for (int nf = 0; nf < 4; nf++)
                mma_tf32(c4[nf], pa, vb[nf][kk]);
        }
        const long orow = ((long)b * N_TOK + rp) * MODEL_D + h * HEAD_D;
#pragma unroll
        for (int nf = 0; nf < 4; nf++) {
            const int d0 = nf * 8 + tg * 2;
            if (rp < N_TOK) {
                float2 v; v.x = c4[nf][0]; v.y = c4[nf][1];
                *(float2*)(g_att + orow + d0) = v;
            }
            if (rp + 8 < N_TOK) {
                float2 v; v.x = c4[nf][2]; v.y = c4[nf][3];
                *(float2*)(g_att + orow + 8 * MODEL_D + d0) = v;
            }
        }
    }
}

// ---------------------------------------------------------------------------
extern "C" void kernel_launch(void* const* d_in, const int* in_sizes, int n_in,
                              void* d_out, int out_size)
{
    (void)in_sizes; (void)n_in; (void)out_size;
    const float* x      = (const float*)d_in[0];
    const float* mask   = (const float*)d_in[1];
    const float* table  = (const float*)d_in[2];
    const float* qkv_w  = (const float*)d_in[3];
    const float* qkv_b  = (const float*)d_in[4];
    const float* proj_w = (const float*)d_in[5];
    const float* proj_b = (const float*)d_in[6];
    const int*   rpi    = (const int*)d_in[7];
    float* out = (float*)d_out;

    cudaFuncSetAttribute(gemm_big<0>, cudaFuncAttributeMaxDynamicSharedMemorySize, GEMM_SMEMB);
    cudaFuncSetAttribute(gemm_big<1>, cudaFuncAttributeMaxDynamicSharedMemorySize, GEMM_SMEMB);
    cudaFuncSetAttribute(attn_kernel2, cudaFuncAttributeMaxDynamicSharedMemorySize, ATTN_SMEMB);

    // K0: fuse rel-pos bias gather + shift mask -> g_bm (7.4MB, L2-resident)
    bias_precompute<<<dim3(NWIN, N_HEADS), 256>>>(table, rpi, mask);
    // K1: qkv projection (M=401408, N=1152, K=384) -> g_q/g_k/g_v
    gemm_big<0><<<dim3(M_TOT / 256, 1152 / 128), 256, GEMM_SMEMB>>>(x, qkv_w, qkv_b, nullptr);
    // K2: windowed attention -> g_att
    attn_kernel2<<<dim3(B_WIN, N_HEADS / 4), 128, ATTN_SMEMB>>>();
    // K3: output projection (M=401408, N=384, K=384) -> out
    gemm_big<1><<<dim3(M_TOT / 256, 384 / 128), 256, GEMM_SMEMB>>>(nullptr, proj_w, proj_b, out);
}

// round 15
// speedup vs baseline: 1.5602x; 1.1202x over previous
#include <cuda_runtime.h>
#include <cstdint>
#include <cstddef>

// ---------------------------------------------------------------------------
// Swin window attention, legacy tf32 mma.sync (tcgen05 blocked at compute_103).
// R11 decoded profile (ncu dur field is ms): K1=3.89ms K3=1.30ms K2~0.8ms.
// GEMMs are 5.2ms of 6.0ms at tensor=30%, 2 warps/SMSP. This round:
//   GEMM v3: 512 thr (16 warps, 8Mx2N, warp tile 32x64), cp.async staging
//   with commit/wait pipeline, cvt.rna on fragments post-LDS. 4 warps/SMSP.
// K0/K2 byte-identical to the R11 pass (control).
// ---------------------------------------------------------------------------

#define N_TOK   49
#define N_HEADS 12
#define HEAD_D  32
#define MODEL_D 384
#define NWIN    64
#define B_WIN   8192
#define M_TOT   (B_WIN * N_TOK)          // 401408
#define ATTN_SCALE 0.17677669529663687f  // 1/sqrt(32)

__device__ float g_q[(size_t)B_WIN * N_HEADS * N_TOK * HEAD_D];
__device__ float g_k[(size_t)B_WIN * N_HEADS * N_TOK * HEAD_D];
__device__ float g_v[(size_t)B_WIN * N_HEADS * N_TOK * HEAD_D];
__device__ float g_att[(size_t)B_WIN * N_TOK * MODEL_D];
__device__ float g_bm[(size_t)NWIN * N_HEADS * N_TOK * N_TOK];   // bias+mask, 7.4MB

__device__ __forceinline__ uint32_t f2tf(float f) {
    uint32_t u;
    asm("cvt.rna.tf32.f32 %0, %1;" : "=r"(u) : "f"(f));
    return u;
}

__device__ __forceinline__ void mma_tf32(float d[4], const uint32_t a[4], const uint32_t b[2]) {
    asm volatile(
        "mma.sync.aligned.m16n8k8.row.col.f32.tf32.tf32.f32 "
        "{%0,%1,%2,%3}, {%4,%5,%6,%7}, {%8,%9}, {%0,%1,%2,%3};\n"
        : "+f"(d[0]), "+f"(d[1]), "+f"(d[2]), "+f"(d[3])
        : "r"(a[0]), "r"(a[1]), "r"(a[2]), "r"(a[3]),
          "r"(b[0]), "r"(b[1]));
}

__device__ __forceinline__ uint32_t smem_u32(const void* p) {
    uint32_t a;
    asm("{ .reg .u64 t; cvta.to.shared.u64 t, %1; cvt.u32.u64 %0, t; }"
        : "=r"(a) : "l"(p));
    return a;
}

#define CP_ASYNC16(dst_u32, src_ptr) \
    asm volatile("cp.async.ca.shared.global [%0], [%1], 16;" \
                 :: "r"(dst_u32), "l"(src_ptr) : "memory")
#define CP_COMMIT() asm volatile("cp.async.commit_group;" ::: "memory")
#define CP_WAIT(n)  asm volatile("cp.async.wait_group %0;" :: "n"(n) : "memory")

// ---------------------------------------------------------------------------
// K0: g_bm[w][h][i][j] = table[rpi[i,j]*H + h] + mask[w][i][j]   (unchanged)
// ---------------------------------------------------------------------------
__global__ void bias_precompute(const float* __restrict__ table,
                                const int*   __restrict__ rpi,
                                const float* __restrict__ mask)
{
    const int w = blockIdx.x;
    const int h = blockIdx.y;
    float* dst = g_bm + ((size_t)w * N_HEADS + h) * (N_TOK * N_TOK);
    const float* mk = mask + (size_t)w * (N_TOK * N_TOK);
    for (int ij = threadIdx.x; ij < N_TOK * N_TOK; ij += blockDim.x)
        dst[ij] = table[rpi[ij] * N_HEADS + h] + mk[ij];
}

// ---------------------------------------------------------------------------
// GEMM v3: C[M, 128-per-ny] = A[M,384] @ W^T + bias
// 512 threads = 16 warps (8 M-warps x 2 N-warps), warp tile 32x64.
// Block tile 256x128, BK=16, cp.async double-buffered (pitch 20 floats,
// rows 80B so 16B-aligned cp.async dst). Raw fp32 in smem; cvt.rna on frags.
// ---------------------------------------------------------------------------
#define GP 20
// floats: A buf0 [0,5120), A buf1 [5120,10240), B buf0 [10240,12800),
//         B buf1 [12800,15360), bias [15360,15488)
#define GEMM_SMEMF (2 * 256 * GP + 2 * 128 * GP + 128)
#define GEMM_SMEMB (GEMM_SMEMF * 4)   // 61952 B

template<int EPI>
__global__ void __launch_bounds__(512, 1) gemm_v3(
    const float* __restrict__ A, const float* __restrict__ W,
    const float* __restrict__ bias, float* __restrict__ out)
{
    extern __shared__ float sm[];
    const uint32_t sbase = smem_u32(sm);

    const int tid  = threadIdx.x;
    const int lane = tid & 31;
    const int warp = tid >> 5;
    const int g    = lane >> 2;
    const int tg   = lane & 3;
    const int wm   = (warp & 7) * 32;    // 8 M-warps
    const int wn   = (warp >> 3) * 64;   // 2 N-warps

    const long m0 = (long)blockIdx.x * 256;
    const int  ny = blockIdx.y;
    const int  n0 = ny * 128;

    float* biasS = sm + 15360;
    if (tid < 128) biasS[tid] = bias[n0 + tid];

    const float* Abase = (EPI == 0) ? A : (const float*)g_att;

    float acc[2][8][4];
#pragma unroll
    for (int mf = 0; mf < 2; mf++)
#pragma unroll
        for (int nf = 0; nf < 8; nf++)
#pragma unroll
            for (int r = 0; r < 4; r++) acc[mf][nf][r] = 0.f;

    // ---- stage chunk 0 ----
    {
        const int kc = 0;
#pragma unroll
        for (int i = 0; i < 2; i++) {
            const int fa  = tid * 2 + i;
            const int row = fa >> 2, c4 = fa & 3;
            CP_ASYNC16(sbase + (row * GP + c4 * 4) * 4,
                       Abase + (m0 + row) * MODEL_D + kc + c4 * 4);
        }
        {
            const int row = tid >> 2, c4 = tid & 3;
            CP_ASYNC16(sbase + (10240 + row * GP + c4 * 4) * 4,
                       W + (long)(n0 + row) * MODEL_D + kc + c4 * 4);
        }
        CP_COMMIT();
    }

#pragma unroll 1
    for (int c = 0; c < 24; c++) {
        const int buf = c & 1;
        if (c < 23) {
            const int kc  = (c + 1) * 16;
            const int nb  = (c + 1) & 1;
#pragma unroll
            for (int i = 0; i < 2; i++) {
                const int fa  = tid * 2 + i;
                const int row = fa >> 2, c4 = fa & 3;
                CP_ASYNC16(sbase + (nb * 5120 + row * GP + c4 * 4) * 4,
                           Abase + (m0 + row) * MODEL_D + kc + c4 * 4);
            }
            {
                const int row = tid >> 2, c4 = tid & 3;
                CP_ASYNC16(sbase + (10240 + nb * 2560 + row * GP + c4 * 4) * 4,
                           W + (long)(n0 + row) * MODEL_D + kc + c4 * 4);
            }
            CP_COMMIT();
            CP_WAIT(1);
        } else {
            CP_WAIT(0);
        }
        __syncthreads();

        const float* Ab = sm + buf * 5120;
        const float* Bb = sm + 10240 + buf * 2560;
#pragma unroll 1
        for (int kk = 0; kk < 2; kk++) {
            const int k0 = kk * 8;
            uint32_t af[2][4];
#pragma unroll
            for (int mf = 0; mf < 2; mf++) {
                const int r = wm + mf * 16 + g;
                af[mf][0] = f2tf(Ab[r * GP + k0 + tg]);
                af[mf][1] = f2tf(Ab[(r + 8) * GP + k0 + tg]);
                af[mf][2] = f2tf(Ab[r * GP + k0 + tg + 4]);
                af[mf][3] = f2tf(Ab[(r + 8) * GP + k0 + tg + 4]);
            }
            uint32_t bf[8][2];
#pragma unroll
            for (int nf = 0; nf < 8; nf++) {
                const int cr = wn + nf * 8 + g;
                bf[nf][0] = f2tf(Bb[cr * GP + k0 + tg]);
                bf[nf][1] = f2tf(Bb[cr * GP + k0 + tg + 4]);
            }
#pragma unroll
            for (int mf = 0; mf < 2; mf++)
#pragma unroll
                for (int nf = 0; nf < 8; nf++)
                    mma_tf32(acc[mf][nf], af[mf], bf[nf]);
        }
        __syncthreads();
    }

    // ---------------- epilogue ----------------
    const int t3      = (EPI == 0) ? (ny / 3) : 0;
    const int rembase = (EPI == 0) ? ((ny % 3) * 128) : 0;
    float* dstT = (EPI == 0) ? ((t3 == 0) ? g_q : ((t3 == 1) ? g_k : g_v)) : out;
    const float scl = (EPI == 0 && t3 == 0) ? ATTN_SCALE : 1.0f;

#pragma unroll
    for (int mf = 0; mf < 2; mf++) {
#pragma unroll
        for (int h2 = 0; h2 < 2; h2++) {
            const long m = m0 + wm + mf * 16 + g + h2 * 8;
            long rowoff;
            if (EPI == 0) {
                const long bb = m / N_TOK;
                const int  ii = (int)(m - bb * N_TOK);
                rowoff = bb * (N_HEADS * N_TOK * HEAD_D) + (long)ii * HEAD_D;
            } else {
                rowoff = m * MODEL_D;
            }
#pragma unroll
            for (int nf = 0; nf < 8; nf++) {
                const int cc = wn + nf * 8 + tg * 2;
                float2 v;
                v.x = (acc[mf][nf][h2 * 2 + 0] + biasS[cc])     * scl;
                v.y = (acc[mf][nf][h2 * 2 + 1] + biasS[cc + 1]) * scl;
                if (EPI == 0) {
                    const int rc = rembase + cc;
                    const int hh = rc >> 5, dd = rc & 31;
                    *(float2*)(dstT + rowoff + (long)hh * (N_TOK * HEAD_D) + dd) = v;
                } else {
                    *(float2*)(dstT + rowoff + n0 + cc) = v;
                }
            }
        }
    }
}

// ---------------------------------------------------------------------------
// K2 (unchanged from R11 pass): one warp per (window, head), S/P-only smem,
// Q/K/V frags gmem->reg, g_bm pre-summed. 3 blocks/SM.
// ---------------------------------------------------------------------------
#define SSP 60
#define ATTN_WARP_F (64 * SSP)
#define ATTN_SMEMB  (4 * ATTN_WARP_F * 4)

__global__ void __launch_bounds__(128, 3) attn_kernel2()
{
    extern __shared__ float sm2[];
    const int lane = threadIdx.x & 31;
    const int warp = threadIdx.x >> 5;
    const int g    = lane >> 2;
    const int tg   = lane & 3;
    const int b    = blockIdx.x;
    const int h    = blockIdx.y * 4 + warp;
    float* ss = sm2 + warp * ATTN_WARP_F;

    const size_t base = ((size_t)b * N_HEADS + h) * (N_TOK * HEAD_D);
    const float* gq = g_q + base;
    const float* gk = g_k + base;
    const float* gv = g_v + base;
    const float* bm = g_bm + ((size_t)(b & (NWIN - 1)) * N_HEADS + h) * (N_TOK * N_TOK);

    uint32_t kb[7][4][2];
#pragma unroll
    for (int nf = 0; nf < 7; nf++) {
        const int c = nf * 8 + g;
#pragma unroll
        for (int kk = 0; kk < 4; kk++) {
            const int k0 = kk * 8;
            kb[nf][kk][0] = (c < N_TOK) ? f2tf(gk[c * HEAD_D + k0 + tg])     : 0u;
            kb[nf][kk][1] = (c < N_TOK) ? f2tf(gk[c * HEAD_D + k0 + tg + 4]) : 0u;
        }
    }

#pragma unroll 1
    for (int mf = 0; mf < 4; mf++) {
        const int rq = mf * 16 + g;
        uint32_t qa[4][4];
#pragma unroll
        for (int kk = 0; kk < 4; kk++) {
            const int k0 = kk * 8;
            qa[kk][0] = (rq < N_TOK)     ? f2tf(gq[rq * HEAD_D + k0 + tg])           : 0u;
            qa[kk][1] = (rq + 8 < N_TOK) ? f2tf(gq[(rq + 8) * HEAD_D + k0 + tg])     : 0u;
            qa[kk][2] = (rq < N_TOK)     ? f2tf(gq[rq * HEAD_D + k0 + tg + 4])       : 0u;
            qa[kk][3] = (rq + 8 < N_TOK) ? f2tf(gq[(rq + 8) * HEAD_D + k0 + tg + 4]) : 0u;
        }
        float c7[7][4];
#pragma unroll
        for (int nf = 0; nf < 7; nf++)
#pragma unroll
            for (int r = 0; r < 4; r++) c7[nf][r] = 0.f;
#pragma unroll
        for (int kk = 0; kk < 4; kk++)
#pragma unroll
            for (int nf = 0; nf < 7; nf++)
                mma_tf32(c7[nf], qa[kk], kb[nf][kk]);
#pragma unroll
        for (int nf = 0; nf < 7; nf++) {
#pragma unroll
            for (int r = 0; r < 4; r++) {
                const int i = mf * 16 + g + ((r & 2) ? 8 : 0);
                const int j = nf * 8 + tg * 2 + (r & 1);
                float v = 0.f;
                if (i < N_TOK && j < N_TOK)
                    v = c7[nf][r] + bm[i * N_TOK + j];
                ss[i * SSP + j] = v;
            }
        }
    }
    __syncwarp();

    for (int r = lane; r < N_TOK; r += 32) {
        float* row = ss + r * SSP;
        float mx = row[0];
        for (int j = 1; j < N_TOK; j++) mx = fmaxf(mx, row[j]);
        float sum = 0.f;
        for (int j = 0; j < N_TOK; j++) {
            float e = __expf(row[j] - mx);
            sum += e;
            row[j] = e;
        }
        const float inv = 1.f / sum;
        for (int j = 0; j < N_TOK; j++)
            row[j] = __uint_as_float(f2tf(row[j] * inv));
    }
    __syncwarp();

    uint32_t vb[4][7][2];
#pragma unroll
    for (int nf = 0; nf < 4; nf++) {
        const int d = nf * 8 + g;
#pragma unroll
        for (int kk = 0; kk < 7; kk++) {
            const int j0 = kk * 8;
            vb[nf][kk][0] = (j0 + tg < N_TOK)     ? f2tf(gv[(j0 + tg) * HEAD_D + d])     : 0u;
            vb[nf][kk][1] = (j0 + tg + 4 < N_TOK) ? f2tf(gv[(j0 + tg + 4) * HEAD_D + d]) : 0u;
        }
    }

#pragma unroll 1
    for (int mf = 0; mf < 4; mf++) {
        const int rp = mf * 16 + g;
        float c4[4][4];
#pragma unroll
        for (int nf = 0; nf < 4; nf++)
#pragma unroll
            for (int r = 0; r < 4; r++) c4[nf][r] = 0.f;
#pragma unroll
        for (int kk = 0; kk < 7; kk++) {
            const int k0 = kk * 8;
            uint32_t pa[4];
            pa[0] = __float_as_uint(ss[rp * SSP + k0 + tg]);
            pa[1] = __float_as_uint(ss[(rp + 8) * SSP + k0 + tg]);
            pa[2] = __float_as_uint(ss[rp * SSP + k0 + tg + 4]);
            pa[3] = __float_as_uint(ss[(rp + 8) * SSP + k0 + tg + 4]);
#pragma unroll
            for (int nf = 0; nf < 4; nf++)
                mma_tf32(c4[nf], pa, vb[nf][kk]);
        }
        const long orow = ((long)b * N_TOK + rp) * MODEL_D + h * HEAD_D;
#pragma unroll
        for (int nf = 0; nf < 4; nf++) {
            const int d0 = nf * 8 + tg * 2;
            if (rp < N_TOK) {
                float2 v; v.x = c4[nf][0]; v.y = c4[nf][1];
                *(float2*)(g_att + orow + d0) = v;
            }
            if (rp + 8 < N_TOK) {
                float2 v; v.x = c4[nf][2]; v.y = c4[nf][3];
                *(float2*)(g_att + orow + 8 * MODEL_D + d0) = v;
            }
        }
    }
}

// ---------------------------------------------------------------------------
extern "C" void kernel_launch(void* const* d_in, const int* in_sizes, int n_in,
                              void* d_out, int out_size)
{
    (void)in_sizes; (void)n_in; (void)out_size;
    const float* x      = (const float*)d_in[0];
    const float* mask   = (const float*)d_in[1];
    const float* table  = (const float*)d_in[2];
    const float* qkv_w  = (const float*)d_in[3];
    const float* qkv_b  = (const float*)d_in[4];
    const float* proj_w = (const float*)d_in[5];
    const float* proj_b = (const float*)d_in[6];
    const int*   rpi    = (const int*)d_in[7];
    float* out = (float*)d_out;

    cudaFuncSetAttribute(gemm_v3<0>, cudaFuncAttributeMaxDynamicSharedMemorySize, GEMM_SMEMB);
    cudaFuncSetAttribute(gemm_v3<1>, cudaFuncAttributeMaxDynamicSharedMemorySize, GEMM_SMEMB);
    cudaFuncSetAttribute(attn_kernel2, cudaFuncAttributeMaxDynamicSharedMemorySize, ATTN_SMEMB);

    // K0: fuse rel-pos bias gather + shift mask -> g_bm
    bias_precompute<<<dim3(NWIN, N_HEADS), 256>>>(table, rpi, mask);
    // K1: qkv projection (M=401408, N=1152, K=384) -> g_q/g_k/g_v
    gemm_v3<0><<<dim3(M_TOT / 256, 1152 / 128), 512, GEMM_SMEMB>>>(x, qkv_w, qkv_b, nullptr);
    // K2: windowed attention -> g_att
    attn_kernel2<<<dim3(B_WIN, N_HEADS / 4), 128, ATTN_SMEMB>>>();
    // K3: output projection (M=401408, N=384, K=384) -> out
    gemm_v3<1><<<dim3(M_TOT / 256, 384 / 128), 512, GEMM_SMEMB>>>(nullptr, proj_w, proj_b, out);
}